// round 14
// baseline (speedup 1.0000x reference)
#include <cuda_runtime.h>
#include <cuda_fp16.h>
#include <math.h>

#define NNODES 50000
#define NPAD   50048   // padded row count (gemm tiles read full 64-row blocks)
#define NEDGES 800000

// ---------------- device scratch (no allocations allowed) ----------------
__device__ int     g_deg[NNODES];
__device__ int     g_rowptr[NNODES + 1];
__device__ int     g_wr[NNODES];
__device__ int     g_srcs[NEDGES];
__device__ __half2 g_hfh[NNODES * 64];  // transformed features, fp16 [N][128]
__device__ __half  g_h1h[NPAD * 128];   // layer-1 output (relu), fp16 (= exact mma input)
__device__ float   g_el[NNODES * 4];
__device__ float   g_er[NNODES * 4];
__device__ __half  g_wt1[128 * 128];    // W1 transposed [n][k] fp16
__device__ __half  g_wt2[128 * 128];    // W2 transposed [n][k] fp16

// ---------------- fused init: convert W1, W2 + zero degree ----------------
__global__ void k_init(const float* __restrict__ W1, const float* __restrict__ W2) {
    int i = blockIdx.x * blockDim.x + threadIdx.x;
    if (i < 16384) {
        int k = i >> 7, n = i & 127;
        g_wt1[n * 128 + k] = __float2half_rn(W1[k * 128 + n]);
    } else if (i < 32768) {
        int j = i - 16384;
        int k = j >> 7, n = j & 127;
        g_wt2[n * 128 + k] = __float2half_rn(W2[k * 128 + n]);
    } else if (i < 32768 + NNODES) {
        g_deg[i - 32768] = 0;
    }
}

// 4 edges per thread: int4 edge load + 4 independent atomics (MLP 4x)
__global__ void k_hist(const int* __restrict__ dst) {
    int i = blockIdx.x * blockDim.x + threadIdx.x;
    if (i < NEDGES / 4) {
        int4 d = __ldg((const int4*)dst + i);
        atomicAdd(&g_deg[d.x], 1);
        atomicAdd(&g_deg[d.y], 1);
        atomicAdd(&g_deg[d.z], 1);
        atomicAdd(&g_deg[d.w], 1);
    }
}

// single-block exclusive scan of g_deg -> g_rowptr (and g_wr copy)
__global__ void k_scan() {
    __shared__ int ssum[1024];
    int tid = threadIdx.x;
    const int CH = (NNODES + 1023) / 1024;   // 49
    int base = tid * CH;
    int local = 0;
    for (int i = 0; i < CH; i++) {
        int idx = base + i;
        if (idx < NNODES) local += g_deg[idx];
    }
    ssum[tid] = local;
    __syncthreads();
    for (int off = 1; off < 1024; off <<= 1) {
        int v = (tid >= off) ? ssum[tid - off] : 0;
        __syncthreads();
        ssum[tid] += v;
        __syncthreads();
    }
    int run = ssum[tid] - local;   // exclusive prefix
    for (int i = 0; i < CH; i++) {
        int idx = base + i;
        if (idx < NNODES) {
            g_rowptr[idx] = run;
            g_wr[idx] = run;
            run += g_deg[idx];
        }
    }
    if (tid == 1023) g_rowptr[NNODES] = ssum[1023];
}

__global__ void k_fill(const int* __restrict__ src, const int* __restrict__ dst) {
    int i = blockIdx.x * blockDim.x + threadIdx.x;
    if (i < NEDGES / 4) {
        int4 d = __ldg((const int4*)dst + i);
        int4 s = __ldg((const int4*)src + i);
        int p0 = atomicAdd(&g_wr[d.x], 1);
        int p1 = atomicAdd(&g_wr[d.y], 1);
        int p2 = atomicAdd(&g_wr[d.z], 1);
        int p3 = atomicAdd(&g_wr[d.w], 1);
        g_srcs[p0] = s.x;
        g_srcs[p1] = s.y;
        g_srcs[p2] = s.z;
        g_srcs[p3] = s.w;
    }
}

// ---------------- tensor-core GEMM: hf = feat @ W (+ el/er epilogue) --------
// FP16IN=false: feat is fp32 [N][128] (layer 1). FP16IN=true: feat is fp16
// g_h1h (layer 2) and the sA fill is a pure uint4 copy. Fragment loads via
// ldmatrix.x4 (1 LDSM replaces 4 LDS.32; row stride 272 B -> conflict-free).
#define SA_STRIDE 136
#define SB_STRIDE 136
#define GEMM_SMEM (64 * SA_STRIDE * 2 + 128 * SB_STRIDE * 2)   // 52224 bytes

__device__ __forceinline__ void mma16816(float* c, unsigned a0, unsigned a1,
                                         unsigned a2, unsigned a3,
                                         unsigned b0, unsigned b1) {
    asm volatile(
        "mma.sync.aligned.m16n8k16.row.col.f32.f16.f16.f32 "
        "{%0,%1,%2,%3}, {%4,%5,%6,%7}, {%8,%9}, {%0,%1,%2,%3};"
        : "+f"(c[0]), "+f"(c[1]), "+f"(c[2]), "+f"(c[3])
        : "r"(a0), "r"(a1), "r"(a2), "r"(a3), "r"(b0), "r"(b1));
}

__device__ __forceinline__ void ldsm_x4(unsigned& r0, unsigned& r1,
                                        unsigned& r2, unsigned& r3, unsigned addr) {
    asm volatile("ldmatrix.sync.aligned.m8n8.x4.shared.b16 {%0,%1,%2,%3}, [%4];"
                 : "=r"(r0), "=r"(r1), "=r"(r2), "=r"(r3) : "r"(addr));
}

template <bool FP16IN>
__global__ void __launch_bounds__(256) k_gemm(const void* __restrict__ featp,
                                              const __half* __restrict__ wt,
                                              const float* __restrict__ al,
                                              const float* __restrict__ ar) {
    extern __shared__ __half sh[];
    __half* sA  = sh;                      // 64 x 136 (row-major, k contiguous)
    __half* sBt = sh + 64 * SA_STRIDE;     // 128 x 136 (n-major, k contiguous)
    int tid = threadIdx.x;
    int row0 = blockIdx.x * 64;

    // fill sBt: pure coalesced copy of pre-transposed fp16 W (128 rows x 16 uint4)
    const uint4* Wt4 = (const uint4*)wt;
    #pragma unroll 8
    for (int i = tid; i < 2048; i += 256) {
        int n = i >> 4, c = i & 15;
        *(uint4*)&sBt[n * SB_STRIDE + c * 8] = Wt4[i];
    }
    // fill sA = feat tile [64 x 128] fp16
    if (FP16IN) {
        const uint4* F16 = (const uint4*)featp;   // 16 uint4 per row
        #pragma unroll 4
        for (int i = tid; i < 1024; i += 256) {
            int r = i >> 4, c = i & 15;
            *(uint4*)&sA[r * SA_STRIDE + c * 8] = F16[(row0 + r) * 16 + c];
        }
    } else {
        const float4* F4 = (const float4*)featp;
        #pragma unroll 2
        for (int i = tid; i < 2048; i += 256) {
            int r = i >> 5, c4 = i & 31;
            int gr = row0 + r;
            float4 f = (gr < NNODES) ? F4[gr * 32 + c4] : make_float4(0.f, 0.f, 0.f, 0.f);
            *(__half2*)&sA[r * SA_STRIDE + c4 * 4]     = __floats2half2_rn(f.x, f.y);
            *(__half2*)&sA[r * SA_STRIDE + c4 * 4 + 2] = __floats2half2_rn(f.z, f.w);
        }
    }
    __syncthreads();

    int warp = tid >> 5, lane = tid & 31;
    int wm = warp >> 1, wn = warp & 1;
    int g = lane >> 2, t2 = (lane & 3) * 2;
    int mbase = wm * 16;
    int nbase = wn * 64;

    float acc[8][4];
    #pragma unroll
    for (int j = 0; j < 8; j++) {
        acc[j][0] = acc[j][1] = acc[j][2] = acc[j][3] = 0.f;
    }

    // ldmatrix addresses
    unsigned sA_u32 = (unsigned)__cvta_generic_to_shared(sA);
    unsigned sB_u32 = (unsigned)__cvta_generic_to_shared(sBt);
    // A x4: lanes 0-7/8-15 -> rows mbase+(l&15) col 0; lanes 16-31 -> col 8
    unsigned a_addr = sA_u32 +
        ((mbase + (lane & 15)) * SA_STRIDE + (lane >> 4) * 8) * 2;
    // B x4 for j-pair p: lanes 0-7 (j0,k0) / 8-15 (j0,k0+8) / 16-23 (j1,k0) / 24-31 (j1,k0+8)
    int nrow_off = (lane & 7) + ((lane >> 4) & 1) * 8;
    int kcol_off = ((lane >> 3) & 1) * 8;
    unsigned b_addr = sB_u32 + ((nbase + nrow_off) * SB_STRIDE + kcol_off) * 2;
    const unsigned PSTRIDE = 16 * SB_STRIDE * 2;

    #pragma unroll
    for (int ks = 0; ks < 8; ks++) {
        unsigned a0, a1, a2, a3;
        ldsm_x4(a0, a1, a2, a3, a_addr + ks * 32);
        #pragma unroll
        for (int p = 0; p < 4; p++) {
            unsigned b0, b1, b2, b3;
            ldsm_x4(b0, b1, b2, b3, b_addr + p * PSTRIDE + ks * 32);
            mma16816(acc[2 * p],     a0, a1, a2, a3, b0, b1);
            mma16816(acc[2 * p + 1], a0, a1, a2, a3, b2, b3);
        }
    }

    // epilogue: rows r0 = row0+mbase+g, r1 = r0+8. Store fp16 hf; el/er from fp32.
    int r0 = row0 + mbase + g;
    int r1 = r0 + 8;
    __half* hf = (__half*)g_hfh;
    float el0a = 0.f, er0a = 0.f, el1a = 0.f, er1a = 0.f;  // head h0
    float el0b = 0.f, er0b = 0.f, el1b = 0.f, er1b = 0.f;  // head h0+1
    #pragma unroll
    for (int j = 0; j < 8; j++) {
        int n = nbase + j * 8 + t2;
        if (r0 < NNODES)
            *(__half2*)&hf[r0 * 128 + n] = __floats2half2_rn(acc[j][0], acc[j][1]);
        if (r1 < NNODES)
            *(__half2*)&hf[r1 * 128 + n] = __floats2half2_rn(acc[j][2], acc[j][3]);
        float av0 = __ldg(&al[n]), av1 = __ldg(&al[n + 1]);
        float rv0 = __ldg(&ar[n]), rv1 = __ldg(&ar[n + 1]);
        float pe0 = acc[j][0] * av0 + acc[j][1] * av1;
        float pr0 = acc[j][0] * rv0 + acc[j][1] * rv1;
        float pe1 = acc[j][2] * av0 + acc[j][3] * av1;
        float pr1 = acc[j][2] * rv0 + acc[j][3] * rv1;
        if (j < 4) { el0a += pe0; er0a += pr0; el1a += pe1; er1a += pr1; }
        else       { el0b += pe0; er0b += pr0; el1b += pe1; er1b += pr1; }
    }
    #pragma unroll
    for (int off = 1; off <= 2; off <<= 1) {
        el0a += __shfl_xor_sync(0xffffffffu, el0a, off);
        er0a += __shfl_xor_sync(0xffffffffu, er0a, off);
        el1a += __shfl_xor_sync(0xffffffffu, el1a, off);
        er1a += __shfl_xor_sync(0xffffffffu, er1a, off);
        el0b += __shfl_xor_sync(0xffffffffu, el0b, off);
        er0b += __shfl_xor_sync(0xffffffffu, er0b, off);
        el1b += __shfl_xor_sync(0xffffffffu, el1b, off);
        er1b += __shfl_xor_sync(0xffffffffu, er1b, off);
    }
    if ((lane & 3) == 0) {
        int h0 = wn * 2;
        if (r0 < NNODES) {
            g_el[r0 * 4 + h0]     = el0a;  g_er[r0 * 4 + h0]     = er0a;
            g_el[r0 * 4 + h0 + 1] = el0b;  g_er[r0 * 4 + h0 + 1] = er0b;
        }
        if (r1 < NNODES) {
            g_el[r1 * 4 + h0]     = el1a;  g_er[r1 * 4 + h0]     = er1a;
            g_el[r1 * 4 + h0 + 1] = el1b;  g_er[r1 * 4 + h0 + 1] = er1b;
        }
    }
}

// ---------------- warp-per-dst aggregation (R5 version — best) ----------------
__device__ __forceinline__ float lrelu(float x) { return x > 0.f ? x : 0.2f * x; }

template <bool FINAL>
__global__ void __launch_bounds__(256) k_agg(const float* __restrict__ bias,
                                             const float* __restrict__ Wout,
                                             const float* __restrict__ bout,
                                             float* __restrict__ outp) {
    int gw = (blockIdx.x * blockDim.x + threadIdx.x) >> 5;
    int lane = threadIdx.x & 31;
    if (gw >= NNODES) return;
    int n = gw;
    int start = g_rowptr[n], end = g_rowptr[n + 1];
    int h = lane >> 3;
    float er_h = __ldg(&g_er[n * 4 + h]);

    float den = 0.f;
    float4 acc = make_float4(0.f, 0.f, 0.f, 0.f);
    #pragma unroll 4
    for (int j = start; j < end; j++) {
        int s = __ldg(&g_srcs[j]);
        float el = __ldg(&g_el[s * 4 + h]);
        float x = __expf(lrelu(el + er_h));
        den += x;
        uint2 pk = __ldg((const uint2*)(g_hfh + s * 64) + lane);
        float2 v0 = __half22float2(*(__half2*)&pk.x);
        float2 v1 = __half22float2(*(__half2*)&pk.y);
        acc.x += v0.x * x; acc.y += v0.y * x;
        acc.z += v1.x * x; acc.w += v1.y * x;
    }

    float inv = 1.0f / fmaxf(den, 1e-30f);
    float4 b4 = ((const float4*)bias)[lane];
    float4 val;
    val.x = acc.x * inv + b4.x;
    val.y = acc.y * inv + b4.y;
    val.z = acc.z * inv + b4.z;
    val.w = acc.w * inv + b4.w;

    if (!FINAL) {
        val.x = fmaxf(val.x, 0.f); val.y = fmaxf(val.y, 0.f);
        val.z = fmaxf(val.z, 0.f); val.w = fmaxf(val.w, 0.f);
        uint2 pk;
        __half2 h0 = __floats2half2_rn(val.x, val.y);
        __half2 h1 = __floats2half2_rn(val.z, val.w);
        pk.x = *(unsigned*)&h0;
        pk.y = *(unsigned*)&h1;
        ((uint2*)g_h1h)[n * 32 + lane] = pk;
    } else {
        // mean over heads (lanes differing in bits 3,4 hold other heads, same d)
        #pragma unroll
        for (int off = 8; off <= 16; off <<= 1) {
            val.x += __shfl_xor_sync(0xffffffffu, val.x, off);
            val.y += __shfl_xor_sync(0xffffffffu, val.y, off);
            val.z += __shfl_xor_sync(0xffffffffu, val.z, off);
            val.w += __shfl_xor_sync(0xffffffffu, val.w, off);
        }
        val.x = fmaxf(val.x * 0.25f, 0.f);
        val.y = fmaxf(val.y * 0.25f, 0.f);
        val.z = fmaxf(val.z * 0.25f, 0.f);
        val.w = fmaxf(val.w * 0.25f, 0.f);
        int d0 = (lane & 7) * 4;
        float l0 = val.x * Wout[(d0 + 0) * 2 + 0] + val.y * Wout[(d0 + 1) * 2 + 0]
                 + val.z * Wout[(d0 + 2) * 2 + 0] + val.w * Wout[(d0 + 3) * 2 + 0];
        float l1 = val.x * Wout[(d0 + 0) * 2 + 1] + val.y * Wout[(d0 + 1) * 2 + 1]
                 + val.z * Wout[(d0 + 2) * 2 + 1] + val.w * Wout[(d0 + 3) * 2 + 1];
        #pragma unroll
        for (int off = 4; off >= 1; off >>= 1) {
            l0 += __shfl_xor_sync(0xffffffffu, l0, off, 8);
            l1 += __shfl_xor_sync(0xffffffffu, l1, off, 8);
        }
        if (lane == 0) {
            l0 += bout[0];
            l1 += bout[1];
            float m = fmaxf(l0, l1);
            float e0 = __expf(l0 - m), e1 = __expf(l1 - m);
            float s = e0 + e1;
            outp[n * 2 + 0] = e0 / s;
            outp[n * 2 + 1] = e1 / s;
        }
    }
}

// ---------------- launch (serial schedule) ----------------
extern "C" void kernel_launch(void* const* d_in, const int* in_sizes, int n_in,
                              void* d_out, int out_size) {
    const float* in_feat = (const float*)d_in[0];
    const float* W1   = (const float*)d_in[1];
    const float* al1  = (const float*)d_in[2];
    const float* ar1  = (const float*)d_in[3];
    const float* b1   = (const float*)d_in[4];
    const float* W2   = (const float*)d_in[5];
    const float* al2  = (const float*)d_in[6];
    const float* ar2  = (const float*)d_in[7];
    const float* b2   = (const float*)d_in[8];
    const float* Wout = (const float*)d_in[9];
    const float* bout = (const float*)d_in[10];
    const int*   src  = (const int*)d_in[11];
    const int*   dst  = (const int*)d_in[12];
    float* out = (float*)d_out;

    cudaFuncSetAttribute(k_gemm<false>, cudaFuncAttributeMaxDynamicSharedMemorySize, GEMM_SMEM);
    cudaFuncSetAttribute(k_gemm<true>,  cudaFuncAttributeMaxDynamicSharedMemorySize, GEMM_SMEM);

    __half* h1_ptr = nullptr;
    cudaGetSymbolAddress((void**)&h1_ptr, g_h1h);
    __half* wt1_ptr = nullptr;
    cudaGetSymbolAddress((void**)&wt1_ptr, g_wt1);
    __half* wt2_ptr = nullptr;
    cudaGetSymbolAddress((void**)&wt2_ptr, g_wt2);

    int gemm_blocks = (NNODES + 63) / 64;
    int agg_blocks = (NNODES * 32 + 255) / 256;
    int init_threads = 32768 + NNODES;
    int edge4_blocks = (NEDGES / 4 + 255) / 256;

    // fused init (convW1 + convW2 + zero_deg) + CSR + layer 1
    k_init<<<(init_threads + 255) / 256, 256>>>(W1, W2);
    k_hist<<<edge4_blocks, 256>>>(dst);
    k_scan<<<1, 1024>>>();
    k_gemm<false><<<gemm_blocks, 256, GEMM_SMEM>>>(in_feat, wt1_ptr, al1, ar1);
    k_fill<<<edge4_blocks, 256>>>(src, dst);
    k_agg<false><<<agg_blocks, 256>>>(b1, Wout, bout, out);

    // layer 2 + head-mean + projection + softmax
    k_gemm<true><<<gemm_blocks, 256, GEMM_SMEM>>>(h1_ptr, wt2_ptr, al2, ar2);
    k_agg<true><<<agg_blocks, 256>>>(b2, Wout, bout, out);
}

// round 15
// speedup vs baseline: 1.0531x; 1.0531x over previous
#include <cuda_runtime.h>
#include <cuda_fp16.h>
#include <math.h>

#define NNODES 50000
#define NPAD   50048   // padded row count (gemm tiles read full 64-row blocks)
#define NEDGES 800000

// ---------------- device scratch (no allocations allowed) ----------------
__device__ int     g_deg[NNODES];
__device__ int     g_rowptr[NNODES + 1];
__device__ int     g_wr[NNODES];
__device__ int     g_srcs[NEDGES];
__device__ __half2 g_hfh[NNODES * 64];  // transformed features, fp16 [N][128]
__device__ __half  g_h1h[NPAD * 128];   // layer-1 output (relu), fp16 (= exact mma input)
__device__ float   g_el[NNODES * 4];
__device__ float   g_er[NNODES * 4];
__device__ __half  g_wt1[128 * 128];    // W1 transposed [n][k] fp16
__device__ __half  g_wt2[128 * 128];    // W2 transposed [n][k] fp16

// ---------------- fused init: convert W1, W2 + zero degree ----------------
__global__ void k_init(const float* __restrict__ W1, const float* __restrict__ W2) {
    int i = blockIdx.x * blockDim.x + threadIdx.x;
    if (i < 16384) {
        int k = i >> 7, n = i & 127;
        g_wt1[n * 128 + k] = __float2half_rn(W1[k * 128 + n]);
    } else if (i < 32768) {
        int j = i - 16384;
        int k = j >> 7, n = j & 127;
        g_wt2[n * 128 + k] = __float2half_rn(W2[k * 128 + n]);
    } else if (i < 32768 + NNODES) {
        g_deg[i - 32768] = 0;
    }
}

// scalar, one edge per thread (R12 form — 4-per-thread atomics regressed)
__global__ void k_hist(const int* __restrict__ dst) {
    int i = blockIdx.x * blockDim.x + threadIdx.x;
    if (i < NEDGES) atomicAdd(&g_deg[dst[i]], 1);
}

// single-block exclusive scan of g_deg -> g_rowptr (and g_wr copy)
__global__ void k_scan() {
    __shared__ int ssum[1024];
    int tid = threadIdx.x;
    const int CH = (NNODES + 1023) / 1024;   // 49
    int base = tid * CH;
    int local = 0;
    for (int i = 0; i < CH; i++) {
        int idx = base + i;
        if (idx < NNODES) local += g_deg[idx];
    }
    ssum[tid] = local;
    __syncthreads();
    for (int off = 1; off < 1024; off <<= 1) {
        int v = (tid >= off) ? ssum[tid - off] : 0;
        __syncthreads();
        ssum[tid] += v;
        __syncthreads();
    }
    int run = ssum[tid] - local;   // exclusive prefix
    for (int i = 0; i < CH; i++) {
        int idx = base + i;
        if (idx < NNODES) {
            g_rowptr[idx] = run;
            g_wr[idx] = run;
            run += g_deg[idx];
        }
    }
    if (tid == 1023) g_rowptr[NNODES] = ssum[1023];
}

__global__ void k_fill(const int* __restrict__ src, const int* __restrict__ dst) {
    int i = blockIdx.x * blockDim.x + threadIdx.x;
    if (i < NEDGES) {
        int d = dst[i];
        int p = atomicAdd(&g_wr[d], 1);
        g_srcs[p] = src[i];
    }
}

// ---------------- tensor-core GEMM: hf = feat @ W (+ el/er epilogue) --------
// FP16IN=false: feat is fp32 [N][128] (layer 1). FP16IN=true: feat is fp16
// g_h1h (layer 2), sA fill is a pure uint4 copy. Fragment loads via
// ldmatrix.x4. Carveout hint + launch_bounds(256,4) target 4 CTAs/SM.
#define SA_STRIDE 136
#define SB_STRIDE 136
#define GEMM_SMEM (64 * SA_STRIDE * 2 + 128 * SB_STRIDE * 2)   // 52224 bytes

__device__ __forceinline__ void mma16816(float* c, unsigned a0, unsigned a1,
                                         unsigned a2, unsigned a3,
                                         unsigned b0, unsigned b1) {
    asm volatile(
        "mma.sync.aligned.m16n8k16.row.col.f32.f16.f16.f32 "
        "{%0,%1,%2,%3}, {%4,%5,%6,%7}, {%8,%9}, {%0,%1,%2,%3};"
        : "+f"(c[0]), "+f"(c[1]), "+f"(c[2]), "+f"(c[3])
        : "r"(a0), "r"(a1), "r"(a2), "r"(a3), "r"(b0), "r"(b1));
}

__device__ __forceinline__ void ldsm_x4(unsigned& r0, unsigned& r1,
                                        unsigned& r2, unsigned& r3, unsigned addr) {
    asm volatile("ldmatrix.sync.aligned.m8n8.x4.shared.b16 {%0,%1,%2,%3}, [%4];"
                 : "=r"(r0), "=r"(r1), "=r"(r2), "=r"(r3) : "r"(addr));
}

template <bool FP16IN>
__global__ void __launch_bounds__(256, 4) k_gemm(const void* __restrict__ featp,
                                                 const __half* __restrict__ wt,
                                                 const float* __restrict__ al,
                                                 const float* __restrict__ ar) {
    extern __shared__ __half sh[];
    __half* sA  = sh;                      // 64 x 136 (row-major, k contiguous)
    __half* sBt = sh + 64 * SA_STRIDE;     // 128 x 136 (n-major, k contiguous)
    int tid = threadIdx.x;
    int row0 = blockIdx.x * 64;

    // fill sBt: pure coalesced copy of pre-transposed fp16 W (128 rows x 16 uint4)
    const uint4* Wt4 = (const uint4*)wt;
    #pragma unroll 8
    for (int i = tid; i < 2048; i += 256) {
        int n = i >> 4, c = i & 15;
        *(uint4*)&sBt[n * SB_STRIDE + c * 8] = Wt4[i];
    }
    // fill sA = feat tile [64 x 128] fp16
    if (FP16IN) {
        const uint4* F16 = (const uint4*)featp;   // 16 uint4 per row
        #pragma unroll 4
        for (int i = tid; i < 1024; i += 256) {
            int r = i >> 4, c = i & 15;
            *(uint4*)&sA[r * SA_STRIDE + c * 8] = F16[(row0 + r) * 16 + c];
        }
    } else {
        const float4* F4 = (const float4*)featp;
        #pragma unroll 2
        for (int i = tid; i < 2048; i += 256) {
            int r = i >> 5, c4 = i & 31;
            int gr = row0 + r;
            float4 f = (gr < NNODES) ? F4[gr * 32 + c4] : make_float4(0.f, 0.f, 0.f, 0.f);
            *(__half2*)&sA[r * SA_STRIDE + c4 * 4]     = __floats2half2_rn(f.x, f.y);
            *(__half2*)&sA[r * SA_STRIDE + c4 * 4 + 2] = __floats2half2_rn(f.z, f.w);
        }
    }
    __syncthreads();

    int warp = tid >> 5, lane = tid & 31;
    int wm = warp >> 1, wn = warp & 1;
    int g = lane >> 2, t2 = (lane & 3) * 2;
    int mbase = wm * 16;
    int nbase = wn * 64;

    float acc[8][4];
    #pragma unroll
    for (int j = 0; j < 8; j++) {
        acc[j][0] = acc[j][1] = acc[j][2] = acc[j][3] = 0.f;
    }

    // ldmatrix addresses
    unsigned sA_u32 = (unsigned)__cvta_generic_to_shared(sA);
    unsigned sB_u32 = (unsigned)__cvta_generic_to_shared(sBt);
    unsigned a_addr = sA_u32 +
        ((mbase + (lane & 15)) * SA_STRIDE + (lane >> 4) * 8) * 2;
    int nrow_off = (lane & 7) + ((lane >> 4) & 1) * 8;
    int kcol_off = ((lane >> 3) & 1) * 8;
    unsigned b_addr = sB_u32 + ((nbase + nrow_off) * SB_STRIDE + kcol_off) * 2;
    const unsigned PSTRIDE = 16 * SB_STRIDE * 2;

    #pragma unroll
    for (int ks = 0; ks < 8; ks++) {
        unsigned a0, a1, a2, a3;
        ldsm_x4(a0, a1, a2, a3, a_addr + ks * 32);
        #pragma unroll
        for (int p = 0; p < 4; p++) {
            unsigned b0, b1, b2, b3;
            ldsm_x4(b0, b1, b2, b3, b_addr + p * PSTRIDE + ks * 32);
            mma16816(acc[2 * p],     a0, a1, a2, a3, b0, b1);
            mma16816(acc[2 * p + 1], a0, a1, a2, a3, b2, b3);
        }
    }

    // epilogue: rows r0 = row0+mbase+g, r1 = r0+8. Store fp16 hf; el/er from fp32.
    int r0 = row0 + mbase + g;
    int r1 = r0 + 8;
    __half* hf = (__half*)g_hfh;
    float el0a = 0.f, er0a = 0.f, el1a = 0.f, er1a = 0.f;  // head h0
    float el0b = 0.f, er0b = 0.f, el1b = 0.f, er1b = 0.f;  // head h0+1
    #pragma unroll
    for (int j = 0; j < 8; j++) {
        int n = nbase + j * 8 + t2;
        if (r0 < NNODES)
            *(__half2*)&hf[r0 * 128 + n] = __floats2half2_rn(acc[j][0], acc[j][1]);
        if (r1 < NNODES)
            *(__half2*)&hf[r1 * 128 + n] = __floats2half2_rn(acc[j][2], acc[j][3]);
        float av0 = __ldg(&al[n]), av1 = __ldg(&al[n + 1]);
        float rv0 = __ldg(&ar[n]), rv1 = __ldg(&ar[n + 1]);
        float pe0 = acc[j][0] * av0 + acc[j][1] * av1;
        float pr0 = acc[j][0] * rv0 + acc[j][1] * rv1;
        float pe1 = acc[j][2] * av0 + acc[j][3] * av1;
        float pr1 = acc[j][2] * rv0 + acc[j][3] * rv1;
        if (j < 4) { el0a += pe0; er0a += pr0; el1a += pe1; er1a += pr1; }
        else       { el0b += pe0; er0b += pr0; el1b += pe1; er1b += pr1; }
    }
    #pragma unroll
    for (int off = 1; off <= 2; off <<= 1) {
        el0a += __shfl_xor_sync(0xffffffffu, el0a, off);
        er0a += __shfl_xor_sync(0xffffffffu, er0a, off);
        el1a += __shfl_xor_sync(0xffffffffu, el1a, off);
        er1a += __shfl_xor_sync(0xffffffffu, er1a, off);
        el0b += __shfl_xor_sync(0xffffffffu, el0b, off);
        er0b += __shfl_xor_sync(0xffffffffu, er0b, off);
        el1b += __shfl_xor_sync(0xffffffffu, el1b, off);
        er1b += __shfl_xor_sync(0xffffffffu, er1b, off);
    }
    if ((lane & 3) == 0) {
        int h0 = wn * 2;
        if (r0 < NNODES) {
            g_el[r0 * 4 + h0]     = el0a;  g_er[r0 * 4 + h0]     = er0a;
            g_el[r0 * 4 + h0 + 1] = el0b;  g_er[r0 * 4 + h0 + 1] = er0b;
        }
        if (r1 < NNODES) {
            g_el[r1 * 4 + h0]     = el1a;  g_er[r1 * 4 + h0]     = er1a;
            g_el[r1 * 4 + h0 + 1] = el1b;  g_er[r1 * 4 + h0 + 1] = er1b;
        }
    }
}

// ---------------- warp-per-dst aggregation (R5 version — best) ----------------
__device__ __forceinline__ float lrelu(float x) { return x > 0.f ? x : 0.2f * x; }

template <bool FINAL>
__global__ void __launch_bounds__(256) k_agg(const float* __restrict__ bias,
                                             const float* __restrict__ Wout,
                                             const float* __restrict__ bout,
                                             float* __restrict__ outp) {
    int gw = (blockIdx.x * blockDim.x + threadIdx.x) >> 5;
    int lane = threadIdx.x & 31;
    if (gw >= NNODES) return;
    int n = gw;
    int start = g_rowptr[n], end = g_rowptr[n + 1];
    int h = lane >> 3;
    float er_h = __ldg(&g_er[n * 4 + h]);

    float den = 0.f;
    float4 acc = make_float4(0.f, 0.f, 0.f, 0.f);
    #pragma unroll 4
    for (int j = start; j < end; j++) {
        int s = __ldg(&g_srcs[j]);
        float el = __ldg(&g_el[s * 4 + h]);
        float x = __expf(lrelu(el + er_h));
        den += x;
        uint2 pk = __ldg((const uint2*)(g_hfh + s * 64) + lane);
        float2 v0 = __half22float2(*(__half2*)&pk.x);
        float2 v1 = __half22float2(*(__half2*)&pk.y);
        acc.x += v0.x * x; acc.y += v0.y * x;
        acc.z += v1.x * x; acc.w += v1.y * x;
    }

    float inv = 1.0f / fmaxf(den, 1e-30f);
    float4 b4 = ((const float4*)bias)[lane];
    float4 val;
    val.x = acc.x * inv + b4.x;
    val.y = acc.y * inv + b4.y;
    val.z = acc.z * inv + b4.z;
    val.w = acc.w * inv + b4.w;

    if (!FINAL) {
        val.x = fmaxf(val.x, 0.f); val.y = fmaxf(val.y, 0.f);
        val.z = fmaxf(val.z, 0.f); val.w = fmaxf(val.w, 0.f);
        uint2 pk;
        __half2 h0 = __floats2half2_rn(val.x, val.y);
        __half2 h1 = __floats2half2_rn(val.z, val.w);
        pk.x = *(unsigned*)&h0;
        pk.y = *(unsigned*)&h1;
        ((uint2*)g_h1h)[n * 32 + lane] = pk;
    } else {
        // mean over heads (lanes differing in bits 3,4 hold other heads, same d)
        #pragma unroll
        for (int off = 8; off <= 16; off <<= 1) {
            val.x += __shfl_xor_sync(0xffffffffu, val.x, off);
            val.y += __shfl_xor_sync(0xffffffffu, val.y, off);
            val.z += __shfl_xor_sync(0xffffffffu, val.z, off);
            val.w += __shfl_xor_sync(0xffffffffu, val.w, off);
        }
        val.x = fmaxf(val.x * 0.25f, 0.f);
        val.y = fmaxf(val.y * 0.25f, 0.f);
        val.z = fmaxf(val.z * 0.25f, 0.f);
        val.w = fmaxf(val.w * 0.25f, 0.f);
        int d0 = (lane & 7) * 4;
        float l0 = val.x * Wout[(d0 + 0) * 2 + 0] + val.y * Wout[(d0 + 1) * 2 + 0]
                 + val.z * Wout[(d0 + 2) * 2 + 0] + val.w * Wout[(d0 + 3) * 2 + 0];
        float l1 = val.x * Wout[(d0 + 0) * 2 + 1] + val.y * Wout[(d0 + 1) * 2 + 1]
                 + val.z * Wout[(d0 + 2) * 2 + 1] + val.w * Wout[(d0 + 3) * 2 + 1];
        #pragma unroll
        for (int off = 4; off >= 1; off >>= 1) {
            l0 += __shfl_xor_sync(0xffffffffu, l0, off, 8);
            l1 += __shfl_xor_sync(0xffffffffu, l1, off, 8);
        }
        if (lane == 0) {
            l0 += bout[0];
            l1 += bout[1];
            float m = fmaxf(l0, l1);
            float e0 = __expf(l0 - m), e1 = __expf(l1 - m);
            float s = e0 + e1;
            outp[n * 2 + 0] = e0 / s;
            outp[n * 2 + 1] = e1 / s;
        }
    }
}

// ---------------- launch (serial schedule) ----------------
extern "C" void kernel_launch(void* const* d_in, const int* in_sizes, int n_in,
                              void* d_out, int out_size) {
    const float* in_feat = (const float*)d_in[0];
    const float* W1   = (const float*)d_in[1];
    const float* al1  = (const float*)d_in[2];
    const float* ar1  = (const float*)d_in[3];
    const float* b1   = (const float*)d_in[4];
    const float* W2   = (const float*)d_in[5];
    const float* al2  = (const float*)d_in[6];
    const float* ar2  = (const float*)d_in[7];
    const float* b2   = (const float*)d_in[8];
    const float* Wout = (const float*)d_in[9];
    const float* bout = (const float*)d_in[10];
    const int*   src  = (const int*)d_in[11];
    const int*   dst  = (const int*)d_in[12];
    float* out = (float*)d_out;

    cudaFuncSetAttribute(k_gemm<false>, cudaFuncAttributeMaxDynamicSharedMemorySize, GEMM_SMEM);
    cudaFuncSetAttribute(k_gemm<true>,  cudaFuncAttributeMaxDynamicSharedMemorySize, GEMM_SMEM);
    // Carveout hint: request max shared split so 4 CTAs (4 x 52 KB) fit per SM.
    cudaFuncSetAttribute(k_gemm<false>, cudaFuncAttributePreferredSharedMemoryCarveout, 100);
    cudaFuncSetAttribute(k_gemm<true>,  cudaFuncAttributePreferredSharedMemoryCarveout, 100);

    __half* h1_ptr = nullptr;
    cudaGetSymbolAddress((void**)&h1_ptr, g_h1h);
    __half* wt1_ptr = nullptr;
    cudaGetSymbolAddress((void**)&wt1_ptr, g_wt1);
    __half* wt2_ptr = nullptr;
    cudaGetSymbolAddress((void**)&wt2_ptr, g_wt2);

    int gemm_blocks = (NNODES + 63) / 64;
    int agg_blocks = (NNODES * 32 + 255) / 256;
    int init_threads = 32768 + NNODES;

    // fused init (convW1 + convW2 + zero_deg) + CSR + layer 1
    k_init<<<(init_threads + 255) / 256, 256>>>(W1, W2);
    k_hist<<<(NEDGES + 255) / 256, 256>>>(dst);
    k_scan<<<1, 1024>>>();
    k_gemm<false><<<gemm_blocks, 256, GEMM_SMEM>>>(in_feat, wt1_ptr, al1, ar1);
    k_fill<<<(NEDGES + 255) / 256, 256>>>(src, dst);
    k_agg<false><<<agg_blocks, 256>>>(b1, Wout, bout, out);

    // layer 2 + head-mean + projection + softmax
    k_gemm<true><<<gemm_blocks, 256, GEMM_SMEM>>>(h1_ptr, wt2_ptr, al2, ar2);
    k_agg<true><<<agg_blocks, 256>>>(b2, Wout, bout, out);
}

// round 16
// speedup vs baseline: 1.5183x; 1.4418x over previous
#include <cuda_runtime.h>
#include <cuda_fp16.h>
#include <math.h>

#define NNODES 50000
#define NPAD   50048   // padded row count (= NTILES*64)
#define NEDGES 800000
#define NTILES 782

// ---------------- device scratch (no allocations allowed) ----------------
__device__ int     g_deg[NNODES];
__device__ int     g_rowptr[NNODES + 1];
__device__ int     g_wr[NNODES];
__device__ int     g_srcs[NEDGES];
__device__ int     g_tilectr[2];        // persistent-gemm tile counters
__device__ __half2 g_hfh[NNODES * 64];  // transformed features, fp16 [N][128]
__device__ __half  g_h1h[NPAD * 128];   // layer-1 output (relu), fp16
__device__ float   g_el[NNODES * 4];
__device__ float   g_er[NNODES * 4];
__device__ __half  g_wt1[128 * 128];    // W1 transposed [n][k] fp16
__device__ __half  g_wt2[128 * 128];    // W2 transposed [n][k] fp16

// ---------------- fused init: convert W1, W2 + zero degree + counters -------
__global__ void k_init(const float* __restrict__ W1, const float* __restrict__ W2) {
    int i = blockIdx.x * blockDim.x + threadIdx.x;
    if (i < 16384) {
        int k = i >> 7, n = i & 127;
        g_wt1[n * 128 + k] = __float2half_rn(W1[k * 128 + n]);
    } else if (i < 32768) {
        int j = i - 16384;
        int k = j >> 7, n = j & 127;
        g_wt2[n * 128 + k] = __float2half_rn(W2[k * 128 + n]);
    } else if (i < 32768 + NNODES) {
        g_deg[i - 32768] = 0;
    } else if (i < 32768 + NNODES + 2) {
        g_tilectr[i - 32768 - NNODES] = 0;
    }
}

// scalar, one edge per thread (4-per-thread atomics regressed in R14)
__global__ void k_hist(const int* __restrict__ dst) {
    int i = blockIdx.x * blockDim.x + threadIdx.x;
    if (i < NEDGES) atomicAdd(&g_deg[dst[i]], 1);
}

// single-block exclusive scan, smem-staged with coalesced global access
__global__ void k_scan() {
    extern __shared__ int sd[];          // NNODES ints (196 KB dynamic)
    __shared__ int ssum[1024];
    int tid = threadIdx.x;

    // coalesced load of deg into smem
    for (int i = tid; i < NNODES; i += 1024) sd[i] = g_deg[i];
    __syncthreads();

    const int CH = (NNODES + 1023) / 1024;   // 49
    int base = tid * CH;
    int local = 0;
    #pragma unroll 7
    for (int i = 0; i < CH; i++) {
        int idx = base + i;
        if (idx < NNODES) local += sd[idx];   // bank 17t mod 32: conflict-free
    }
    ssum[tid] = local;
    __syncthreads();
    for (int off = 1; off < 1024; off <<= 1) {
        int v = (tid >= off) ? ssum[tid - off] : 0;
        __syncthreads();
        ssum[tid] += v;
        __syncthreads();
    }
    int run = ssum[tid] - local;   // exclusive prefix
    #pragma unroll 7
    for (int i = 0; i < CH; i++) {
        int idx = base + i;
        if (idx < NNODES) {
            int d = sd[idx];
            sd[idx] = run;          // overwrite in-place with prefix
            run += d;
        }
    }
    __syncthreads();
    // coalesced write-out
    for (int i = tid; i < NNODES; i += 1024) {
        int v = sd[i];
        g_rowptr[i] = v;
        g_wr[i] = v;
    }
    if (tid == 1023) g_rowptr[NNODES] = ssum[1023];
}

__global__ void k_fill(const int* __restrict__ src, const int* __restrict__ dst) {
    int i = blockIdx.x * blockDim.x + threadIdx.x;
    if (i < NEDGES) {
        int d = dst[i];
        int p = atomicAdd(&g_wr[d], 1);
        g_srcs[p] = src[i];
    }
}

// ---------------- persistent tensor-core GEMM (+ el/er epilogue) ------------
// Grid 592 (4 CTAs/SM). Each CTA fills the B tile ONCE, then steals 64-row
// tiles via an atomic counter until done (work-conserving; no wave tail).
#define SA_STRIDE 136
#define SB_STRIDE 136
#define GEMM_SMEM (64 * SA_STRIDE * 2 + 128 * SB_STRIDE * 2)   // 52224 bytes

__device__ __forceinline__ void mma16816(float* c, unsigned a0, unsigned a1,
                                         unsigned a2, unsigned a3,
                                         unsigned b0, unsigned b1) {
    asm volatile(
        "mma.sync.aligned.m16n8k16.row.col.f32.f16.f16.f32 "
        "{%0,%1,%2,%3}, {%4,%5,%6,%7}, {%8,%9}, {%0,%1,%2,%3};"
        : "+f"(c[0]), "+f"(c[1]), "+f"(c[2]), "+f"(c[3])
        : "r"(a0), "r"(a1), "r"(a2), "r"(a3), "r"(b0), "r"(b1));
}

__device__ __forceinline__ void ldsm_x4(unsigned& r0, unsigned& r1,
                                        unsigned& r2, unsigned& r3, unsigned addr) {
    asm volatile("ldmatrix.sync.aligned.m8n8.x4.shared.b16 {%0,%1,%2,%3}, [%4];"
                 : "=r"(r0), "=r"(r1), "=r"(r2), "=r"(r3) : "r"(addr));
}

template <bool FP16IN>
__global__ void __launch_bounds__(256, 4) k_gemm(const void* __restrict__ featp,
                                                 const __half* __restrict__ wt,
                                                 const float* __restrict__ al,
                                                 const float* __restrict__ ar,
                                                 int* __restrict__ ctr) {
    extern __shared__ __half sh[];
    __half* sA  = sh;                      // 64 x 136 (row-major, k contiguous)
    __half* sBt = sh + 64 * SA_STRIDE;     // 128 x 136 (n-major, k contiguous)
    __shared__ int s_tile;
    int tid = threadIdx.x;

    int warp = tid >> 5, lane = tid & 31;
    int wm = warp >> 1, wn = warp & 1;
    int g = lane >> 2, t2 = (lane & 3) * 2;
    int mbase = wm * 16;
    int nbase = wn * 64;

    unsigned sA_u32 = (unsigned)__cvta_generic_to_shared(sA);
    unsigned sB_u32 = (unsigned)__cvta_generic_to_shared(sBt);
    unsigned a_addr = sA_u32 +
        ((mbase + (lane & 15)) * SA_STRIDE + (lane >> 4) * 8) * 2;
    int nrow_off = (lane & 7) + ((lane >> 4) & 1) * 8;
    int kcol_off = ((lane >> 3) & 1) * 8;
    unsigned b_addr = sB_u32 + ((nbase + nrow_off) * SB_STRIDE + kcol_off) * 2;
    const unsigned PSTRIDE = 16 * SB_STRIDE * 2;

    bool first = true;
    while (true) {
        if (tid == 0) s_tile = atomicAdd(ctr, 1);
        __syncthreads();
        int tile = s_tile;
        if (tile >= NTILES) break;
        int row0 = tile * 64;

        if (first) {
            // fill sBt once: pure coalesced copy of pre-transposed fp16 W
            const uint4* Wt4 = (const uint4*)wt;
            #pragma unroll 8
            for (int i = tid; i < 2048; i += 256) {
                int n = i >> 4, c = i & 15;
                *(uint4*)&sBt[n * SB_STRIDE + c * 8] = Wt4[i];
            }
            first = false;
        }
        // fill sA = feat tile [64 x 128] fp16
        if (FP16IN) {
            const uint4* F16 = (const uint4*)featp;
            #pragma unroll 4
            for (int i = tid; i < 1024; i += 256) {
                int r = i >> 4, c = i & 15;
                *(uint4*)&sA[r * SA_STRIDE + c * 8] = F16[(row0 + r) * 16 + c];
            }
        } else {
            const float4* F4 = (const float4*)featp;
            #pragma unroll 2
            for (int i = tid; i < 2048; i += 256) {
                int r = i >> 5, c4 = i & 31;
                int gr = row0 + r;
                float4 f = (gr < NNODES) ? F4[gr * 32 + c4]
                                         : make_float4(0.f, 0.f, 0.f, 0.f);
                *(__half2*)&sA[r * SA_STRIDE + c4 * 4]     = __floats2half2_rn(f.x, f.y);
                *(__half2*)&sA[r * SA_STRIDE + c4 * 4 + 2] = __floats2half2_rn(f.z, f.w);
            }
        }
        __syncthreads();

        float acc[8][4];
        #pragma unroll
        for (int j = 0; j < 8; j++) {
            acc[j][0] = acc[j][1] = acc[j][2] = acc[j][3] = 0.f;
        }

        #pragma unroll
        for (int ks = 0; ks < 8; ks++) {
            unsigned a0, a1, a2, a3;
            ldsm_x4(a0, a1, a2, a3, a_addr + ks * 32);
            #pragma unroll
            for (int p = 0; p < 4; p++) {
                unsigned b0, b1, b2, b3;
                ldsm_x4(b0, b1, b2, b3, b_addr + p * PSTRIDE + ks * 32);
                mma16816(acc[2 * p],     a0, a1, a2, a3, b0, b1);
                mma16816(acc[2 * p + 1], a0, a1, a2, a3, b2, b3);
            }
        }

        // epilogue: rows r0/r1. Store fp16 hf; el/er from fp32 accumulators.
        int r0 = row0 + mbase + g;
        int r1 = r0 + 8;
        __half* hf = (__half*)g_hfh;
        float el0a = 0.f, er0a = 0.f, el1a = 0.f, er1a = 0.f;
        float el0b = 0.f, er0b = 0.f, el1b = 0.f, er1b = 0.f;
        #pragma unroll
        for (int j = 0; j < 8; j++) {
            int n = nbase + j * 8 + t2;
            if (r0 < NNODES)
                *(__half2*)&hf[r0 * 128 + n] = __floats2half2_rn(acc[j][0], acc[j][1]);
            if (r1 < NNODES)
                *(__half2*)&hf[r1 * 128 + n] = __floats2half2_rn(acc[j][2], acc[j][3]);
            float av0 = __ldg(&al[n]), av1 = __ldg(&al[n + 1]);
            float rv0 = __ldg(&ar[n]), rv1 = __ldg(&ar[n + 1]);
            float pe0 = acc[j][0] * av0 + acc[j][1] * av1;
            float pr0 = acc[j][0] * rv0 + acc[j][1] * rv1;
            float pe1 = acc[j][2] * av0 + acc[j][3] * av1;
            float pr1 = acc[j][2] * rv0 + acc[j][3] * rv1;
            if (j < 4) { el0a += pe0; er0a += pr0; el1a += pe1; er1a += pr1; }
            else       { el0b += pe0; er0b += pr0; el1b += pe1; er1b += pr1; }
        }
        #pragma unroll
        for (int off = 1; off <= 2; off <<= 1) {
            el0a += __shfl_xor_sync(0xffffffffu, el0a, off);
            er0a += __shfl_xor_sync(0xffffffffu, er0a, off);
            el1a += __shfl_xor_sync(0xffffffffu, el1a, off);
            er1a += __shfl_xor_sync(0xffffffffu, er1a, off);
            el0b += __shfl_xor_sync(0xffffffffu, el0b, off);
            er0b += __shfl_xor_sync(0xffffffffu, er0b, off);
            el1b += __shfl_xor_sync(0xffffffffu, el1b, off);
            er1b += __shfl_xor_sync(0xffffffffu, er1b, off);
        }
        if ((lane & 3) == 0) {
            int h0 = wn * 2;
            if (r0 < NNODES) {
                g_el[r0 * 4 + h0]     = el0a;  g_er[r0 * 4 + h0]     = er0a;
                g_el[r0 * 4 + h0 + 1] = el0b;  g_er[r0 * 4 + h0 + 1] = er0b;
            }
            if (r1 < NNODES) {
                g_el[r1 * 4 + h0]     = el1a;  g_er[r1 * 4 + h0]     = er1a;
                g_el[r1 * 4 + h0 + 1] = el1b;  g_er[r1 * 4 + h0 + 1] = er1b;
            }
        }
        __syncthreads();   // protect sA / s_tile before next iteration
    }
}

// ---------------- warp-per-dst aggregation (R5 version — best) ----------------
__device__ __forceinline__ float lrelu(float x) { return x > 0.f ? x : 0.2f * x; }

template <bool FINAL>
__global__ void __launch_bounds__(256) k_agg(const float* __restrict__ bias,
                                             const float* __restrict__ Wout,
                                             const float* __restrict__ bout,
                                             float* __restrict__ outp) {
    int gw = (blockIdx.x * blockDim.x + threadIdx.x) >> 5;
    int lane = threadIdx.x & 31;
    if (gw >= NNODES) return;
    int n = gw;
    int start = g_rowptr[n], end = g_rowptr[n + 1];
    int h = lane >> 3;
    float er_h = __ldg(&g_er[n * 4 + h]);

    float den = 0.f;
    float4 acc = make_float4(0.f, 0.f, 0.f, 0.f);
    #pragma unroll 4
    for (int j = start; j < end; j++) {
        int s = __ldg(&g_srcs[j]);
        float el = __ldg(&g_el[s * 4 + h]);
        float x = __expf(lrelu(el + er_h));
        den += x;
        uint2 pk = __ldg((const uint2*)(g_hfh + s * 64) + lane);
        float2 v0 = __half22float2(*(__half2*)&pk.x);
        float2 v1 = __half22float2(*(__half2*)&pk.y);
        acc.x += v0.x * x; acc.y += v0.y * x;
        acc.z += v1.x * x; acc.w += v1.y * x;
    }

    float inv = 1.0f / fmaxf(den, 1e-30f);
    float4 b4 = ((const float4*)bias)[lane];
    float4 val;
    val.x = acc.x * inv + b4.x;
    val.y = acc.y * inv + b4.y;
    val.z = acc.z * inv + b4.z;
    val.w = acc.w * inv + b4.w;

    if (!FINAL) {
        val.x = fmaxf(val.x, 0.f); val.y = fmaxf(val.y, 0.f);
        val.z = fmaxf(val.z, 0.f); val.w = fmaxf(val.w, 0.f);
        uint2 pk;
        __half2 h0 = __floats2half2_rn(val.x, val.y);
        __half2 h1 = __floats2half2_rn(val.z, val.w);
        pk.x = *(unsigned*)&h0;
        pk.y = *(unsigned*)&h1;
        ((uint2*)g_h1h)[n * 32 + lane] = pk;
    } else {
        #pragma unroll
        for (int off = 8; off <= 16; off <<= 1) {
            val.x += __shfl_xor_sync(0xffffffffu, val.x, off);
            val.y += __shfl_xor_sync(0xffffffffu, val.y, off);
            val.z += __shfl_xor_sync(0xffffffffu, val.z, off);
            val.w += __shfl_xor_sync(0xffffffffu, val.w, off);
        }
        val.x = fmaxf(val.x * 0.25f, 0.f);
        val.y = fmaxf(val.y * 0.25f, 0.f);
        val.z = fmaxf(val.z * 0.25f, 0.f);
        val.w = fmaxf(val.w * 0.25f, 0.f);
        int d0 = (lane & 7) * 4;
        float l0 = val.x * Wout[(d0 + 0) * 2 + 0] + val.y * Wout[(d0 + 1) * 2 + 0]
                 + val.z * Wout[(d0 + 2) * 2 + 0] + val.w * Wout[(d0 + 3) * 2 + 0];
        float l1 = val.x * Wout[(d0 + 0) * 2 + 1] + val.y * Wout[(d0 + 1) * 2 + 1]
                 + val.z * Wout[(d0 + 2) * 2 + 1] + val.w * Wout[(d0 + 3) * 2 + 1];
        #pragma unroll
        for (int off = 4; off >= 1; off >>= 1) {
            l0 += __shfl_xor_sync(0xffffffffu, l0, off, 8);
            l1 += __shfl_xor_sync(0xffffffffu, l1, off, 8);
        }
        if (lane == 0) {
            l0 += bout[0];
            l1 += bout[1];
            float m = fmaxf(l0, l1);
            float e0 = __expf(l0 - m), e1 = __expf(l1 - m);
            float s = e0 + e1;
            outp[n * 2 + 0] = e0 / s;
            outp[n * 2 + 1] = e1 / s;
        }
    }
}

// ---------------- launch (serial schedule) ----------------
extern "C" void kernel_launch(void* const* d_in, const int* in_sizes, int n_in,
                              void* d_out, int out_size) {
    const float* in_feat = (const float*)d_in[0];
    const float* W1   = (const float*)d_in[1];
    const float* al1  = (const float*)d_in[2];
    const float* ar1  = (const float*)d_in[3];
    const float* b1   = (const float*)d_in[4];
    const float* W2   = (const float*)d_in[5];
    const float* al2  = (const float*)d_in[6];
    const float* ar2  = (const float*)d_in[7];
    const float* b2   = (const float*)d_in[8];
    const float* Wout = (const float*)d_in[9];
    const float* bout = (const float*)d_in[10];
    const int*   src  = (const int*)d_in[11];
    const int*   dst  = (const int*)d_in[12];
    float* out = (float*)d_out;

    cudaFuncSetAttribute(k_gemm<false>, cudaFuncAttributeMaxDynamicSharedMemorySize, GEMM_SMEM);
    cudaFuncSetAttribute(k_gemm<true>,  cudaFuncAttributeMaxDynamicSharedMemorySize, GEMM_SMEM);
    cudaFuncSetAttribute(k_gemm<false>, cudaFuncAttributePreferredSharedMemoryCarveout, 100);
    cudaFuncSetAttribute(k_gemm<true>,  cudaFuncAttributePreferredSharedMemoryCarveout, 100);
    cudaFuncSetAttribute(k_scan, cudaFuncAttributeMaxDynamicSharedMemorySize, NNODES * 4);

    __half* h1_ptr = nullptr;
    cudaGetSymbolAddress((void**)&h1_ptr, g_h1h);
    __half* wt1_ptr = nullptr;
    cudaGetSymbolAddress((void**)&wt1_ptr, g_wt1);
    __half* wt2_ptr = nullptr;
    cudaGetSymbolAddress((void**)&wt2_ptr, g_wt2);
    int* ctr_ptr = nullptr;
    cudaGetSymbolAddress((void**)&ctr_ptr, g_tilectr);

    int agg_blocks = (NNODES * 32 + 255) / 256;
    int init_threads = 32768 + NNODES + 2;
    const int GEMM_GRID = 592;   // 4 CTAs/SM x 148 SMs, persistent

    // fused init (convW + zero_deg + counters) + CSR + layer 1
    k_init<<<(init_threads + 255) / 256, 256>>>(W1, W2);
    k_hist<<<(NEDGES + 255) / 256, 256>>>(dst);
    k_scan<<<1, 1024, NNODES * 4>>>();
    k_gemm<false><<<GEMM_GRID, 256, GEMM_SMEM>>>(in_feat, wt1_ptr, al1, ar1, ctr_ptr);
    k_fill<<<(NEDGES + 255) / 256, 256>>>(src, dst);
    k_agg<false><<<agg_blocks, 256>>>(b1, Wout, bout, out);

    // layer 2 + head-mean + projection + softmax
    k_gemm<true><<<GEMM_GRID, 256, GEMM_SMEM>>>(h1_ptr, wt2_ptr, al2, ar2, ctr_ptr + 1);
    k_agg<true><<<agg_blocks, 256>>>(b2, Wout, bout, out);
}